// round 6
// baseline (speedup 1.0000x reference)
#include <cuda_runtime.h>
#include <cuda_bf16.h>
#include <cstdint>

#define BB 8
#define NN 10000
#define EE 160000
#define FF 64
#define BN (BB * NN)          // 80000 nodes
#define BE (BB * EE)          // 1280000 edges
#define SCAN_BLKS ((BN + 1023) / 1024)   // 79

// ---- scratch (device globals; no allocation allowed) ----
__device__ int   g_is64;
__device__ int   g_degi[BN];
__device__ float g_dinv[BN];
__device__ int   g_rowstart[BN];
__device__ int   g_cursor[BN];
__device__ int   g_scantmp[BN];
__device__ int   g_partial[SCAN_BLKS];
__device__ int2  g_rc[BE];        // packed (row, col)
__device__ int2  g_csr[BE];       // {col, norm-bits} grouped by row
__device__ float g_t[BN * FF];    // post-linear features
__device__ float g_pA[BN * FF];   // ping
__device__ float g_pB[BN * FF];   // pong

// ---------------------------------------------------------------------------
__device__ __forceinline__ void fma2(unsigned long long& acc,
                                     unsigned long long a,
                                     unsigned long long b) {
    asm("fma.rn.f32x2 %0, %1, %2, %0;" : "+l"(acc) : "l"(a), "l"(b));
}
__device__ __forceinline__ unsigned long long pack2(float lo, float hi) {
    unsigned long long r;
    asm("mov.b64 %0, {%1, %2};" : "=l"(r) : "f"(lo), "f"(hi));
    return r;
}
__device__ __forceinline__ void unpack2(unsigned long long v, float& lo, float& hi) {
    asm("mov.b64 {%0, %1}, %2;" : "=f"(lo), "=f"(hi) : "l"(v));
}

// ---------------------------------------------------------------------------
// zero degrees; thread 0 also detects edge_index width
__global__ void setup_k(const void* ei, int* __restrict__ degp) {
    int i = blockIdx.x * blockDim.x + threadIdx.x;
    for (; i < BN; i += gridDim.x * blockDim.x) degp[i] = 0;
    if (threadIdx.x == 0 && blockIdx.x == 0) {
        const long long* p = (const long long*)ei;
        int ok = 1;
        for (int k = 0; k < 64; k++) {
            long long v = p[k];
            if (v < 0 || v >= NN) { ok = 0; break; }
        }
        g_is64 = ok;
    }
}

// edge pairs -> int32 with per-graph offset (packed int2); degree histogram
__global__ void edges_k(const void* __restrict__ ei) {
    int e = blockIdx.x * blockDim.x + threadIdx.x;
    if (e >= BE) return;
    int r, c;
    if (g_is64) {
        const long long* p = (const long long*)ei;
        r = (int)p[2 * e];
        c = (int)p[2 * e + 1];
    } else {
        const int* p = (const int*)ei;
        r = p[2 * e];
        c = p[2 * e + 1];
    }
    r = min(max(r, 0), NN - 1);
    c = min(max(c, 0), NN - 1);
    int b = e / EE;
    r += b * NN;
    c += b * NN;
    g_rc[e] = make_int2(r, c);
    atomicAdd(&g_degi[r], 1);
}

// ---- two-level exclusive scan of degrees ----
__global__ void __launch_bounds__(1024, 1) scanA_k() {
    __shared__ int warpsum[32];
    int tid = threadIdx.x, lane = tid & 31, wid = tid >> 5;
    int i = blockIdx.x * 1024 + tid;
    int v = (i < BN) ? g_degi[i] : 0;
    int x = v;
#pragma unroll
    for (int off = 1; off < 32; off <<= 1) {
        int y = __shfl_up_sync(0xffffffffu, x, off);
        if (lane >= off) x += y;
    }
    if (lane == 31) warpsum[wid] = x;
    __syncthreads();
    if (wid == 0) {
        int s = warpsum[lane];
        int xs = s;
#pragma unroll
        for (int off = 1; off < 32; off <<= 1) {
            int y = __shfl_up_sync(0xffffffffu, xs, off);
            if (lane >= off) xs += y;
        }
        warpsum[lane] = xs - s;
    }
    __syncthreads();
    int excl = warpsum[wid] + x - v;
    if (i < BN) g_scantmp[i] = excl;
    if (tid == 1023) g_partial[blockIdx.x] = excl + v;
}

__global__ void scanB_k() {
    int lane = threadIdx.x;
    int carry = 0;
    for (int base = 0; base < SCAN_BLKS; base += 32) {
        int idx = base + lane;
        int v = (idx < SCAN_BLKS) ? g_partial[idx] : 0;
        int x = v;
#pragma unroll
        for (int off = 1; off < 32; off <<= 1) {
            int y = __shfl_up_sync(0xffffffffu, x, off);
            if (lane >= off) x += y;
        }
        if (idx < SCAN_BLKS) g_partial[idx] = carry + x - v;
        carry += __shfl_sync(0xffffffffu, x, 31);
    }
}

__global__ void scanC_k() {   // add offsets; fused dinv
    int i = blockIdx.x * blockDim.x + threadIdx.x;
    if (i >= BN) return;
    int start = g_scantmp[i] + g_partial[i >> 10];
    g_rowstart[i] = start;
    g_cursor[i]   = start;
    int d = g_degi[i];
    g_dinv[i] = d > 0 ? rsqrtf((float)d) : 0.f;
}

// scatter edges into CSR slots
__global__ void fill_k() {
    int e = blockIdx.x * blockDim.x + threadIdx.x;
    if (e >= BE) return;
    int2 rc = g_rc[e];
    int pos = atomicAdd(&g_cursor[rc.x], 1);
    float nm = g_dinv[rc.x] * g_dinv[rc.y];
    g_csr[pos] = make_int2(rc.y, __float_as_int(nm));
}

// ---------------------------------------------------------------------------
// t = (relu?)(in) @ W^T + b  — packed f32x2, 4 rows per warp, 32 rows per block
template <bool RELU>
__global__ void __launch_bounds__(256)
linear_k(const float* __restrict__ in, const float* __restrict__ W,
         const float* __restrict__ bias, float* __restrict__ out) {
    __shared__ float2 sWp[64 * 32];   // [k][l] = (W[l][k], W[l+32][k])
    __shared__ float2 sx2[32 * 64];   // [r][k] = (v,v) replicated
    __shared__ float  sb[64];
    int tid = threadIdx.x;
    int row0 = blockIdx.x * 32;

    for (int idx = tid; idx < 2048; idx += 256) {
        int k = idx >> 5, l = idx & 31;
        sWp[idx] = make_float2(W[l * 64 + k], W[(l + 32) * 64 + k]);
    }
    if (tid < 64) sb[tid] = bias[tid];
    for (int idx = tid; idx < 2048; idx += 256) {
        int r = idx >> 6, k = idx & 63;
        float v = in[(size_t)(row0 + r) * 64 + k];
        if (RELU) v = fmaxf(v, 0.f);
        sx2[idx] = make_float2(v, v);
    }
    __syncthreads();

    int w = tid >> 5, l = tid & 31;
    int r0 = w * 4;
    unsigned long long bias2 = pack2(sb[l], sb[l + 32]);
    unsigned long long a0 = bias2, a1 = bias2, a2 = bias2, a3 = bias2;

    const unsigned long long* wp = (const unsigned long long*)sWp;
    const unsigned long long* xp = (const unsigned long long*)sx2;
#pragma unroll
    for (int k = 0; k < 64; k++) {
        unsigned long long wk = wp[k * 32 + l];
        fma2(a0, wk, xp[(r0 + 0) * 64 + k]);
        fma2(a1, wk, xp[(r0 + 1) * 64 + k]);
        fma2(a2, wk, xp[(r0 + 2) * 64 + k]);
        fma2(a3, wk, xp[(r0 + 3) * 64 + k]);
    }
    float lo, hi;
    unpack2(a0, lo, hi); out[(size_t)(row0+r0+0)*64 + l] = lo; out[(size_t)(row0+r0+0)*64 + l + 32] = hi;
    unpack2(a1, lo, hi); out[(size_t)(row0+r0+1)*64 + l] = lo; out[(size_t)(row0+r0+1)*64 + l + 32] = hi;
    unpack2(a2, lo, hi); out[(size_t)(row0+r0+2)*64 + l] = lo; out[(size_t)(row0+r0+2)*64 + l + 32] = hi;
    unpack2(a3, lo, hi); out[(size_t)(row0+r0+3)*64 + l] = lo; out[(size_t)(row0+r0+3)*64 + l + 32] = hi;
}

// ---------------------------------------------------------------------------
// CSR gather SpMM v2: one warp per node, 2 edges per iteration.
// Lane groups of 16: group g handles edge (it*2+g); each lane reads float4
// (16B) of the 256B feature row. Meta via group-uniform __ldg (HW broadcast,
// no shuffles). Epilogue: shfl_xor(16) combine, group 0 stores float4.
__global__ void __launch_bounds__(256, 4)
spmm_k(const float* __restrict__ t, float* __restrict__ out) {
    int warp = (blockIdx.x * blockDim.x + threadIdx.x) >> 5;
    if (warp >= BN) return;
    int lane = threadIdx.x & 31;
    int grp  = lane >> 4;       // 0 or 1
    int sub  = lane & 15;       // float4 slot within the 256B row
    int start = g_rowstart[warp];
    int cnt   = g_degi[warp];

    float4 acc = make_float4(0.f, 0.f, 0.f, 0.f);
    int iters = (cnt + 1) >> 1;
#pragma unroll 4
    for (int it = 0; it < iters; it++) {
        int idx = it * 2 + grp;
        bool ok = idx < cnt;
        int2 meta = ok ? __ldg(&g_csr[start + idx]) : make_int2(0, 0);
        float nm = ok ? __int_as_float(meta.y) : 0.f;
        float4 v = __ldg(reinterpret_cast<const float4*>(
                             t + (size_t)meta.x * 64) + sub);
        acc.x = fmaf(nm, v.x, acc.x);
        acc.y = fmaf(nm, v.y, acc.y);
        acc.z = fmaf(nm, v.z, acc.z);
        acc.w = fmaf(nm, v.w, acc.w);
    }
    // combine the two edge-groups
    acc.x += __shfl_xor_sync(0xffffffffu, acc.x, 16);
    acc.y += __shfl_xor_sync(0xffffffffu, acc.y, 16);
    acc.z += __shfl_xor_sync(0xffffffffu, acc.z, 16);
    acc.w += __shfl_xor_sync(0xffffffffu, acc.w, 16);
    if (grp == 0)
        reinterpret_cast<float4*>(out + (size_t)warp * 64)[sub] = acc;
}

// ---------------------------------------------------------------------------
extern "C" void kernel_launch(void* const* d_in, const int* in_sizes, int n_in,
                              void* d_out, int out_size) {
    const float* x = nullptr;
    const void*  ei = nullptr;
    const float* Ws[3] = {nullptr, nullptr, nullptr};
    const float* bs[3] = {nullptr, nullptr, nullptr};
    int nW = 0, nb = 0;
    for (int i = 0; i < n_in; i++) {
        long long sz = in_sizes[i];
        if (sz == (long long)BN * FF)      x  = (const float*)d_in[i];
        else if (sz == (long long)BE * 2)  ei = d_in[i];
        else if (sz == FF * FF) { if (nW < 3) Ws[nW++] = (const float*)d_in[i]; }
        else if (sz == FF)      { if (nb < 3) bs[nb++] = (const float*)d_in[i]; }
    }
    float* out = (float*)d_out;

    int   *degi;
    float *t, *pA, *pB;
    cudaGetSymbolAddress((void**)&degi, g_degi);
    cudaGetSymbolAddress((void**)&t,    g_t);
    cudaGetSymbolAddress((void**)&pA,   g_pA);
    cudaGetSymbolAddress((void**)&pB,   g_pB);

    const int TPB = 256;
    const int edgeBlocks = (BE + TPB - 1) / TPB;            // 5000
    const int nodeBlocks = (BN + TPB - 1) / TPB;            // 313
    const int spmmBlocks = (BN * 32 + TPB - 1) / TPB;       // 10000
    const int linBlocks  = BN / 32;                         // 2500

    // CSR build
    setup_k<<<nodeBlocks, TPB>>>(ei, degi);
    edges_k<<<edgeBlocks, TPB>>>(ei);
    scanA_k<<<SCAN_BLKS, 1024>>>();
    scanB_k<<<1, 32>>>();
    scanC_k<<<nodeBlocks, TPB>>>();
    fill_k<<<edgeBlocks, TPB>>>();

    // layer 1
    linear_k<false><<<linBlocks, TPB>>>(x, Ws[0], bs[0], t);
    spmm_k<<<spmmBlocks, TPB>>>(t, pA);
    // layer 2
    linear_k<true><<<linBlocks, TPB>>>(pA, Ws[1], bs[1], t);
    spmm_k<<<spmmBlocks, TPB>>>(t, pB);
    // layer 3
    linear_k<true><<<linBlocks, TPB>>>(pB, Ws[2], bs[2], t);
    spmm_k<<<spmmBlocks, TPB>>>(t, out);
}